// round 3
// baseline (speedup 1.0000x reference)
#include <cuda_runtime.h>

// Problem constants (fixed by setup_inputs)
constexpr int B = 4, H = 1024, W = 1024;
constexpr int TX = 32;          // output tile width
constexpr int TY = 32;          // output tile height (4 rows per thread)
constexpr int HX = TX + 10;     // 42: halo tile width
constexpr int HY = TY + 10;     // 42: halo tile height

typedef unsigned long long u64; // carrier for packed f32x2 (even/odd reg pair)

__device__ __forceinline__ u64 pk(float lo, float hi) {
    u64 r; asm("mov.b64 %0,{%1,%2};" : "=l"(r) : "f"(lo), "f"(hi)); return r;
}
__device__ __forceinline__ void up(u64 v, float& lo, float& hi) {
    asm("mov.b64 {%0,%1},%2;" : "=f"(lo), "=f"(hi) : "l"(v));
}
__device__ __forceinline__ u64 mul2(u64 a, u64 b) {
    u64 d; asm("mul.rn.f32x2 %0,%1,%2;" : "=l"(d) : "l"(a), "l"(b)); return d;
}
__device__ __forceinline__ u64 add2(u64 a, u64 b) {
    u64 d; asm("add.rn.f32x2 %0,%1,%2;" : "=l"(d) : "l"(a), "l"(b)); return d;
}
__device__ __forceinline__ u64 fma2(u64 a, u64 b, u64 c) {
    u64 d; asm("fma.rn.f32x2 %0,%1,%2,%3;" : "=l"(d) : "l"(a), "l"(b), "l"(c)); return d;
}
__device__ __forceinline__ float rcpa(float x) {
    float r; asm("rcp.approx.f32 %0,%1;" : "=f"(r) : "f"(x)); return r;
}

#define MK 1e30f
// Q[m+3][sc] = (dist - 0.5) for dy = m-5 (m = 0..10 valid rows), with disk-mask
// zeros replaced by 1e30 so saturatef(coc - c1) == 0 there. Rows m outside
// [0,10] (Q[0..2], Q[14..16]) are all-MK pads used by inactive pair elements.
__device__ constexpr float Q[17][11] = {
  {MK,MK,MK,MK,MK,MK,MK,MK,MK,MK,MK},
  {MK,MK,MK,MK,MK,MK,MK,MK,MK,MK,MK},
  {MK,MK,MK,MK,MK,MK,MK,MK,MK,MK,MK},
  {MK,MK,MK,4.885164807f,4.599019514f,4.5f,4.599019514f,4.885164807f,MK,MK,MK},
  {MK,MK,4.5f,3.972135955f,3.623105626f,3.5f,3.623105626f,3.972135955f,4.5f,MK,MK},
  {MK,4.5f,3.742640687f,3.105551276f,2.662277660f,2.5f,2.662277660f,3.105551276f,3.742640687f,4.5f,MK},
  {4.885164807f,3.972135955f,3.105551276f,2.328427125f,1.736067977f,1.5f,1.736067977f,2.328427125f,3.105551276f,3.972135955f,4.885164807f},
  {4.599019514f,3.623105626f,2.662277660f,1.736067977f,0.914213562f,0.5f,0.914213562f,1.736067977f,2.662277660f,3.623105626f,4.599019514f},
  {4.5f,3.5f,2.5f,1.5f,0.5f,-0.5f,0.5f,1.5f,2.5f,3.5f,4.5f},
  {4.599019514f,3.623105626f,2.662277660f,1.736067977f,0.914213562f,0.5f,0.914213562f,1.736067977f,2.662277660f,3.623105626f,4.599019514f},
  {4.885164807f,3.972135955f,3.105551276f,2.328427125f,1.736067977f,1.5f,1.736067977f,2.328427125f,3.105551276f,3.972135955f,4.885164807f},
  {MK,4.5f,3.742640687f,3.105551276f,2.662277660f,2.5f,2.662277660f,3.105551276f,3.742640687f,4.5f,MK},
  {MK,MK,4.5f,3.972135955f,3.623105626f,3.5f,3.623105626f,3.972135955f,4.5f,MK,MK},
  {MK,MK,MK,4.885164807f,4.599019514f,4.5f,4.599019514f,4.885164807f,MK,MK,MK},
  {MK,MK,MK,MK,MK,MK,MK,MK,MK,MK,MK},
  {MK,MK,MK,MK,MK,MK,MK,MK,MK,MK,MK},
  {MK,MK,MK,MK,MK,MK,MK,MK,MK,MK,MK}
};

__global__ __launch_bounds__(256, 4)
void scatter_render_kernel(const float* __restrict__ x,
                           const float* __restrict__ lens,
                           float* __restrict__ out)
{
    __shared__ float2 s_ec[HY][HX];   // (exp(4*disp), coc)
    __shared__ float2 s_rg[HY][HX];   // (r, g)
    __shared__ float  s_b [HY][HX];   // b

    const int b   = blockIdx.z;
    const int gx0 = blockIdx.x * TX;
    const int gy0 = blockIdx.y * TY;

    const float scale = fabsf(lens[b]);
    const float* __restrict__ xb = x + (size_t)b * 4 * H * W;
    const float* __restrict__ pr = xb;
    const float* __restrict__ pg = xb + H * W;
    const float* __restrict__ pb = xb + 2 * H * W;
    const float* __restrict__ pd = xb + 3 * H * W;

    // ---- cooperative halo-tile fill (with edge clamp) ----
    const int tid = threadIdx.y * TX + threadIdx.x;
    for (int idx = tid; idx < HY * HX; idx += 256) {
        int yy = idx / HX;
        int xx = idx - yy * HX;
        int sy = gy0 + yy - 5; sy = min(max(sy, 0), H - 1);
        int sx = gx0 + xx - 5; sx = min(max(sx, 0), W - 1);
        int o  = sy * W + sx;
        float d  = pd[o];
        float es = __expf(4.0f * d);
        float cc = scale * fabsf(d);
        s_ec[yy][xx] = make_float2(es, cc);
        s_rg[yy][xx] = make_float2(pr[o], pg[o]);
        s_b [yy][xx] = pb[o];
    }
    __syncthreads();

    // ---- main gather: each thread owns 4 vertically adjacent outputs,
    //      packed as f32x2 pairs (out0,out1) and (out2,out3) ----
    const int tx = threadIdx.x;
    const int ry = 4 * threadIdx.y;

    const float e0 = s_ec[ry + 5][tx + 5].x;
    const float e1 = s_ec[ry + 6][tx + 5].x;
    const float e2 = s_ec[ry + 7][tx + 5].x;
    const float e3 = s_ec[ry + 8][tx + 5].x;
    const u64 ed01 = pk(e0, e1);
    const u64 ed23 = pk(e2, e3);

    u64 aR01 = 0, aG01 = 0, aB01 = 0, aD01 = 0;
    u64 aR23 = 0, aG23 = 0, aB23 = 0, aD23 = 0;

    #pragma unroll
    for (int sr = 0; sr < 14; ++sr) {       // union of the 4 outputs' 11 rows
        #pragma unroll
        for (int sc = 0; sc < 11; ++sc) {
            const float2 ec = s_ec[ry + sr][tx + sc];
            const float2 rg = s_rg[ry + sr][tx + sc];
            const float  bv = s_b [ry + sr][tx + sc];
            const u64 es2 = pk(ec.x, ec.x);
            const u64 rr  = pk(rg.x, rg.x);
            const u64 gg  = pk(rg.y, rg.y);
            const u64 bb  = pk(bv, bv);

            if (sr <= 11) {                 // pair (out0, out1) active rows
                const float w0 = __saturatef(ec.y - Q[sr + 3][sc]);
                const float w1 = __saturatef(ec.y - Q[sr + 2][sc]);
                const u64 num = mul2(pk(w0, w1), es2);
                const u64 den = add2(es2, ed01);
                float d0, d1; up(den, d0, d1);
                const u64 wo = mul2(num, pk(rcpa(d0), rcpa(d1)));
                aR01 = fma2(wo, rr, aR01);
                aG01 = fma2(wo, gg, aG01);
                aB01 = fma2(wo, bb, aB01);
                aD01 = add2(aD01, wo);
            }
            if (sr >= 2) {                  // pair (out2, out3) active rows
                const float w2 = __saturatef(ec.y - Q[sr + 1][sc]);
                const float w3 = __saturatef(ec.y - Q[sr    ][sc]);
                const u64 num = mul2(pk(w2, w3), es2);
                const u64 den = add2(es2, ed23);
                float d0, d1; up(den, d0, d1);
                const u64 wo = mul2(num, pk(rcpa(d0), rcpa(d1)));
                aR23 = fma2(wo, rr, aR23);
                aG23 = fma2(wo, gg, aG23);
                aB23 = fma2(wo, bb, aB23);
                aD23 = add2(aD23, wo);
            }
        }
    }

    // ---- epilogue: normalize and store 4 outputs x 3 channels ----
    const int gx = gx0 + tx;
    const int gy = gy0 + ry;
    float* __restrict__ ob = out + (size_t)b * 3 * H * W;

    float r0,r1,r2,r3, g0,g1,g2,g3, b0,b1,b2,b3, d0,d1,d2,d3;
    up(aR01, r0, r1); up(aR23, r2, r3);
    up(aG01, g0, g1); up(aG23, g2, g3);
    up(aB01, b0, b1); up(aB23, b2, b3);
    up(aD01, d0, d1); up(aD23, d2, d3);

    const float i0 = rcpa(d0 + 1e-8f);
    const float i1 = rcpa(d1 + 1e-8f);
    const float i2 = rcpa(d2 + 1e-8f);
    const float i3 = rcpa(d3 + 1e-8f);

    const int o0 = gy * W + gx;
    ob[o0]                 = r0 * i0;
    ob[o0 + W]             = r1 * i1;
    ob[o0 + 2*W]           = r2 * i2;
    ob[o0 + 3*W]           = r3 * i3;
    ob[H*W + o0]           = g0 * i0;
    ob[H*W + o0 + W]       = g1 * i1;
    ob[H*W + o0 + 2*W]     = g2 * i2;
    ob[H*W + o0 + 3*W]     = g3 * i3;
    ob[2*H*W + o0]         = b0 * i0;
    ob[2*H*W + o0 + W]     = b1 * i1;
    ob[2*H*W + o0 + 2*W]   = b2 * i2;
    ob[2*H*W + o0 + 3*W]   = b3 * i3;
}

extern "C" void kernel_launch(void* const* d_in, const int* in_sizes, int n_in,
                              void* d_out, int out_size)
{
    const float* x    = (const float*)d_in[0];
    const float* lens = (const float*)d_in[1];
    float* out        = (float*)d_out;

    dim3 block(TX, TY / 4, 1);              // 32 x 8 = 256 threads
    dim3 grid(W / TX, H / TY, B);           // 32 x 32 x 4
    scatter_render_kernel<<<grid, block>>>(x, lens, out);
}